// round 1
// baseline (speedup 1.0000x reference)
#include <cuda_runtime.h>

#define BB 8
#define CC 64
#define HH 64
#define WW 64
#define NROI 4096
#define NPER 512   // rois per batch-outer index

// NHWC scratch copy of the feature map (8 MB) — __device__ global, no allocs.
__device__ float g_featT[BB * HH * WW * CC];

// Antiderivative of the bilinear tent kernel max(0, 1-|t|), clipped.
__device__ __forceinline__ float tentI(float t) {
    t = fminf(1.0f, fmaxf(-1.0f, t));
    float a = t + 1.0f;
    float b = 1.0f - t;
    return (t < 0.0f) ? 0.5f * a * a : 1.0f - 0.5f * b * b;
}

// NCHW -> NHWC transpose via 32x32 smem tiles.
// grid: (WW/32, CC/32, BB*HH), block: (32, 32)
__global__ void transpose_nchw_nhwc(const float* __restrict__ feat) {
    __shared__ float tile[32][33];
    int by = blockIdx.z;            // b*HH + y
    int b  = by >> 6;
    int y  = by & 63;
    int c0 = blockIdx.y << 5;
    int x0 = blockIdx.x << 5;
    int tx = threadIdx.x, ty = threadIdx.y;

    // read feat[b, c0+ty, y, x0+tx] — coalesced in x
    tile[ty][tx] = feat[(((b * CC + c0 + ty) * HH + y) * WW) + x0 + tx];
    __syncthreads();
    // write g_featT[b, y, x0+ty, c0+tx] — coalesced in c
    g_featT[((size_t)by * WW + x0 + ty) * CC + c0 + tx] = tile[tx][ty];
}

// One roi per 64 threads (2 warps); 4 rois per 256-thread block.
// Each thread owns one channel and accumulates the separable tent integral.
__global__ __launch_bounds__(256) void proi_kernel(const float* __restrict__ rois,
                                                   float* __restrict__ out) {
    int r = (blockIdx.x << 2) + (threadIdx.x >> 6);
    int c = threadIdx.x & 63;

    // output row r corresponds to (b_outer = r/512, n = r%512);
    // roi storage is [N, B, 5] -> flat (n*8 + b_outer)*5
    int b_out = r >> 9;
    int n     = r & (NPER - 1);
    const float* rp = rois + (size_t)(n * BB + b_out) * 5;

    int   bidx = (int)__ldg(rp + 0);
    float x1   = __ldg(rp + 1);
    float y1   = __ldg(rp + 2);
    float x2   = __ldg(rp + 3);
    float y2   = __ldg(rp + 4);

    int ix0 = max(0, (int)floorf(x1));
    int ix1 = min(WW - 1, (int)ceilf(x2));
    int iy0 = max(0, (int)floorf(y1));
    int iy1 = min(HH - 1, (int)ceilf(y2));
    int nx  = ix1 - ix0 + 1;   // <= 14

    // per-axis weights along x, zero outside [ix0, ix1]
    float wx[14];
#pragma unroll
    for (int ii = 0; ii < 14; ++ii) {
        float fi = (float)(ix0 + ii);
        wx[ii] = tentI(x2 - fi) - tentI(x1 - fi);
    }

    const float* fp = g_featT + (((size_t)bidx * HH + iy0) * WW + ix0) * CC + c;

    float acc = 0.0f;
    for (int j = iy0; j <= iy1; ++j) {
        float wy = tentI(y2 - (float)j) - tentI(y1 - (float)j);
        float racc = 0.0f;
#pragma unroll
        for (int ii = 0; ii < 14; ++ii) {
            if (ii < nx) {                      // uniform across the warp (same roi)
                racc = fmaf(wx[ii], fp[ii * CC], racc);
            }
        }
        acc = fmaf(wy, racc, acc);
        fp += WW * CC;
    }

    // total integral / box area  ==  mean over 7x7 bins of (bin integral / bin area)
    float inv_area = 1.0f / ((x2 - x1) * (y2 - y1));
    out[(size_t)r * CC + c] = acc * inv_area;
}

extern "C" void kernel_launch(void* const* d_in, const int* in_sizes, int n_in,
                              void* d_out, int out_size) {
    const float* feature = (const float*)d_in[0];
    const float* rois    = (const float*)d_in[1];
    float* out           = (float*)d_out;

    dim3 tgrid(WW / 32, CC / 32, BB * HH);
    dim3 tblk(32, 32);
    transpose_nchw_nhwc<<<tgrid, tblk>>>(feature);

    proi_kernel<<<NROI / 4, 256>>>(rois, out);
}

// round 2
// speedup vs baseline: 1.2460x; 1.2460x over previous
#include <cuda_runtime.h>

#define BB 8
#define CC 64
#define HH 64
#define WW 64
#define NROI 4096
#define NPER 512   // rois per batch-outer index

// NHWC scratch copy of the feature map (8 MB), float4-aligned.
__device__ float4 g_featT4[BB * HH * WW * (CC / 4)];

// Antiderivative of the bilinear tent kernel max(0, 1-|t|), clipped.
__device__ __forceinline__ float tentI(float t) {
    t = fminf(1.0f, fmaxf(-1.0f, t));
    float a = t + 1.0f;
    float b = 1.0f - t;
    return (t < 0.0f) ? 0.5f * a * a : 1.0f - 0.5f * b * b;
}

// NCHW -> NHWC transpose via 32x32 smem tiles.
// grid: (WW/32, CC/32, BB*HH), block: (32, 32)
__global__ void transpose_nchw_nhwc(const float* __restrict__ feat) {
    __shared__ float tile[32][33];
    float* featT = (float*)g_featT4;
    int by = blockIdx.z;            // b*HH + y
    int b  = by >> 6;
    int y  = by & 63;
    int c0 = blockIdx.y << 5;
    int x0 = blockIdx.x << 5;
    int tx = threadIdx.x, ty = threadIdx.y;

    tile[ty][tx] = feat[(((b * CC + c0 + ty) * HH + y) * WW) + x0 + tx];
    __syncthreads();
    featT[((size_t)by * WW + x0 + ty) * CC + c0 + tx] = tile[tx][ty];
}

// 2 rois per warp (16 lanes each); each lane owns 4 channels (float4).
// 8 warps/block -> 16 rois per block.
__global__ __launch_bounds__(256) void proi_kernel(const float* __restrict__ rois,
                                                   float* __restrict__ out) {
    int lane = threadIdx.x & 31;
    int warp = threadIdx.x >> 5;
    int half = lane >> 4;           // which roi in this warp
    int li   = lane & 15;           // channel-group index (c = 4*li..4*li+3)
    unsigned hmask = 0xFFFFu << (half << 4);

    int r = (blockIdx.x << 4) + (warp << 1) + half;
    // output row r <-> roi storage (n*B + b_out), r = b_out*512 + n
    int b_out = r >> 9;
    int n     = r & (NPER - 1);
    const float* rp = rois + (size_t)(n * BB + b_out) * 5;

    int   bidx = (int)__ldg(rp + 0);
    float x1   = __ldg(rp + 1);
    float y1   = __ldg(rp + 2);
    float x2   = __ldg(rp + 3);
    float y2   = __ldg(rp + 4);

    int ix0 = max(0, (int)floorf(x1));
    int ix1 = min(WW - 1, (int)ceilf(x2));
    int iy0 = max(0, (int)floorf(y1));
    int iy1 = min(HH - 1, (int)ceilf(y2));
    int nx  = ix1 - ix0 + 1;        // <= 14, uniform per half-warp
    int ny  = iy1 - iy0 + 1;        // <= 14, uniform per half-warp

    // Cooperative weight computation: lane li computes weight for offset li.
    float fx  = (float)(ix0 + li);
    float wxl = tentI(x2 - fx) - tentI(x1 - fx);
    float fy  = (float)(iy0 + li);
    float wyl = tentI(y2 - fy) - tentI(y1 - fy);

    // Gather x-weights into registers (all 32 lanes converged here).
    float wx[14];
#pragma unroll
    for (int ii = 0; ii < 14; ++ii)
        wx[ii] = __shfl_sync(0xFFFFFFFFu, wxl, (half << 4) + ii, 32);

    const float4* fp = g_featT4
        + (((size_t)(bidx * HH + iy0) * WW + ix0) << 4) + li;

    float4 acc = make_float4(0.f, 0.f, 0.f, 0.f);
    for (int j = 0; j < ny; ++j) {
        float wy = __shfl_sync(hmask, wyl, (half << 4) + j, 32);
        float4 racc = make_float4(0.f, 0.f, 0.f, 0.f);
#pragma unroll
        for (int ii = 0; ii < 14; ++ii) {
            if (ii < nx) {          // uniform per half-warp; load predicated off beyond nx
                float4 v = fp[ii << 4];
                racc.x = fmaf(wx[ii], v.x, racc.x);
                racc.y = fmaf(wx[ii], v.y, racc.y);
                racc.z = fmaf(wx[ii], v.z, racc.z);
                racc.w = fmaf(wx[ii], v.w, racc.w);
            }
        }
        acc.x = fmaf(wy, racc.x, acc.x);
        acc.y = fmaf(wy, racc.y, acc.y);
        acc.z = fmaf(wy, racc.z, acc.z);
        acc.w = fmaf(wy, racc.w, acc.w);
        fp += WW << 4;              // next y row
    }

    float inv_area = 1.0f / ((x2 - x1) * (y2 - y1));
    float4 o = make_float4(acc.x * inv_area, acc.y * inv_area,
                           acc.z * inv_area, acc.w * inv_area);
    ((float4*)out)[((size_t)r << 4) + li] = o;
}

extern "C" void kernel_launch(void* const* d_in, const int* in_sizes, int n_in,
                              void* d_out, int out_size) {
    const float* feature = (const float*)d_in[0];
    const float* rois    = (const float*)d_in[1];
    float* out           = (float*)d_out;

    dim3 tgrid(WW / 32, CC / 32, BB * HH);
    dim3 tblk(32, 32);
    transpose_nchw_nhwc<<<tgrid, tblk>>>(feature);

    proi_kernel<<<NROI / 16, 256>>>(rois, out);
}

// round 3
// speedup vs baseline: 1.4267x; 1.1450x over previous
#include <cuda_runtime.h>

#define BB 8
#define CC 64
#define HH 64
#define WW 64
#define NROI 4096
#define NPER 512   // rois per batch-outer index

// NHWC scratch copy of the feature map (8 MB), float4-aligned.
__device__ float4 g_featT4[BB * HH * WW * (CC / 4)];

// Antiderivative of the bilinear tent kernel max(0, 1-|t|), clipped.
__device__ __forceinline__ float tentI(float t) {
    t = fminf(1.0f, fmaxf(-1.0f, t));
    float a = t + 1.0f;
    float b = 1.0f - t;
    return (t < 0.0f) ? 0.5f * a * a : 1.0f - 0.5f * b * b;
}

// NCHW -> NHWC transpose via 32x32 smem tiles.
// grid: (WW/32, CC/32, BB*HH), block: (32, 32)
__global__ void transpose_nchw_nhwc(const float* __restrict__ feat) {
    __shared__ float tile[32][33];
    float* featT = (float*)g_featT4;
    int by = blockIdx.z;            // b*HH + y
    int b  = by >> 6;
    int y  = by & 63;
    int c0 = blockIdx.y << 5;
    int x0 = blockIdx.x << 5;
    int tx = threadIdx.x, ty = threadIdx.y;

    tile[ty][tx] = feat[(((b * CC + c0 + ty) * HH + y) * WW) + x0 + tx];
    __syncthreads();
    featT[((size_t)by * WW + x0 + ty) * CC + c0 + tx] = tile[tx][ty];
}

// 2 warps (64 lanes) per roi: 16 channel-lanes (float4 each) x 4-way y-split.
// 256-thread block handles 4 rois. Grid = NROI/4 = 1024 blocks.
__global__ __launch_bounds__(256) void proi_kernel(const float* __restrict__ rois,
                                                   float* __restrict__ out) {
    __shared__ float4 partial[8][16];

    int lane  = threadIdx.x & 31;
    int warp  = threadIdx.x >> 5;
    int roiIB = warp >> 1;              // roi within block: 0..3
    int wIR   = warp & 1;               // warp within roi pair
    int li    = lane & 15;              // channel-group lane (c = 4*li..4*li+3)
    int half  = lane >> 4;
    int hg    = (wIR << 1) + half;      // y-phase 0..3

    int r = (blockIdx.x << 2) + roiIB;
    // output row r <-> roi storage (n*B + b_out), r = b_out*512 + n
    int b_out = r >> 9;
    int n     = r & (NPER - 1);
    const float* rp = rois + (size_t)(n * BB + b_out) * 5;

    int   bidx = (int)__ldg(rp + 0);
    float x1   = __ldg(rp + 1);
    float y1   = __ldg(rp + 2);
    float x2   = __ldg(rp + 3);
    float y2   = __ldg(rp + 4);

    int ix0 = max(0, (int)floorf(x1));
    int ix1 = min(WW - 1, (int)ceilf(x2));
    int iy0 = max(0, (int)floorf(y1));
    int iy1 = min(HH - 1, (int)ceilf(y2));
    int nx  = ix1 - ix0 + 1;            // <= 14, uniform per roi (warp pair)
    int ny  = iy1 - iy0 + 1;            // <= 14, uniform per roi

    // Cooperative weights: lane li computes weight for offset li (replicated
    // in both halves so shuffles stay within each half-warp).
    float fx  = (float)(ix0 + li);
    float wxl = tentI(x2 - fx) - tentI(x1 - fx);
    float fy  = (float)(iy0 + li);
    float wyl = tentI(y2 - fy) - tentI(y1 - fy);

    float wx[14];
#pragma unroll
    for (int ii = 0; ii < 14; ++ii)
        wx[ii] = __shfl_sync(0xFFFFFFFFu, wxl, (half << 4) + ii, 32);

    const float4* fp = g_featT4
        + (((size_t)((bidx * HH + iy0 + hg) * WW) + ix0) << 4) + li;

    float4 acc = make_float4(0.f, 0.f, 0.f, 0.f);
    int trips = (ny + 3) >> 2;          // uniform across the roi's warps
    for (int k = 0; k < trips; ++k) {
        int j = hg + (k << 2);
        bool act = (j < ny);
        float wy = __shfl_sync(0xFFFFFFFFu, wyl, (half << 4) + (j & 15), 32);
        if (act) {
            float4 racc = make_float4(0.f, 0.f, 0.f, 0.f);
#pragma unroll
            for (int ii = 0; ii < 14; ++ii) {
                if (ii < nx) {
                    float4 v = fp[ii << 4];
                    racc.x = fmaf(wx[ii], v.x, racc.x);
                    racc.y = fmaf(wx[ii], v.y, racc.y);
                    racc.z = fmaf(wx[ii], v.z, racc.z);
                    racc.w = fmaf(wx[ii], v.w, racc.w);
                }
            }
            acc.x = fmaf(wy, racc.x, acc.x);
            acc.y = fmaf(wy, racc.y, acc.y);
            acc.z = fmaf(wy, racc.z, acc.z);
            acc.w = fmaf(wy, racc.w, acc.w);
        }
        fp += (WW << 4) << 2;           // advance 4 y-rows
    }

    // Combine the two halves of this warp.
    acc.x += __shfl_xor_sync(0xFFFFFFFFu, acc.x, 16, 32);
    acc.y += __shfl_xor_sync(0xFFFFFFFFu, acc.y, 16, 32);
    acc.z += __shfl_xor_sync(0xFFFFFFFFu, acc.z, 16, 32);
    acc.w += __shfl_xor_sync(0xFFFFFFFFu, acc.w, 16, 32);

    if (half == 0) partial[warp][li] = acc;
    __syncthreads();

    // Combine the warp pair and write out.
    if (wIR == 0 && half == 0) {
        float4 a = partial[warp][li];
        float4 b = partial[warp + 1][li];
        float inv_area = 1.0f / ((x2 - x1) * (y2 - y1));
        float4 o = make_float4((a.x + b.x) * inv_area,
                               (a.y + b.y) * inv_area,
                               (a.z + b.z) * inv_area,
                               (a.w + b.w) * inv_area);
        ((float4*)out)[((size_t)r << 4) + li] = o;
    }
}

extern "C" void kernel_launch(void* const* d_in, const int* in_sizes, int n_in,
                              void* d_out, int out_size) {
    const float* feature = (const float*)d_in[0];
    const float* rois    = (const float*)d_in[1];
    float* out           = (float*)d_out;

    dim3 tgrid(WW / 32, CC / 32, BB * HH);
    dim3 tblk(32, 32);
    transpose_nchw_nhwc<<<tgrid, tblk>>>(feature);

    proi_kernel<<<NROI / 4, 256>>>(rois, out);
}

// round 4
// speedup vs baseline: 1.4459x; 1.0135x over previous
#include <cuda_runtime.h>

#define BB 8
#define CC 64
#define HH 64
#define WW 64
#define NROI 4096
#define NPER 512   // rois per batch-outer index
#define CLAMPB 50  // 64 - 14: window base clamp so base+13 <= 63

// NHWC scratch copy of the feature map (8 MB), float4-aligned.
__device__ float4 g_featT4[BB * HH * WW * (CC / 4)];

// Antiderivative of the bilinear tent kernel max(0, 1-|t|), clipped.
__device__ __forceinline__ float tentI(float t) {
    t = fminf(1.0f, fmaxf(-1.0f, t));
    float a = t + 1.0f;
    float b = 1.0f - t;
    return (t < 0.0f) ? 0.5f * a * a : 1.0f - 0.5f * b * b;
}

// NCHW -> NHWC transpose via 32x32 smem tiles.
// grid: (WW/32, CC/32, BB*HH), block: (32, 32)
__global__ void transpose_nchw_nhwc(const float* __restrict__ feat) {
    __shared__ float tile[32][33];
    float* featT = (float*)g_featT4;
    int by = blockIdx.z;            // b*HH + y
    int b  = by >> 6;
    int y  = by & 63;
    int c0 = blockIdx.y << 5;
    int x0 = blockIdx.x << 5;
    int tx = threadIdx.x, ty = threadIdx.y;

    tile[ty][tx] = feat[(((b * CC + c0 + ty) * HH + y) * WW) + x0 + tx];
    __syncthreads();
    featT[((size_t)by * WW + x0 + ty) * CC + c0 + tx] = tile[tx][ty];
}

// 4 warps (128 lanes) per roi: 16 channel-lanes (float4) x 8-way y-split,
// 2 rows per thread (j = hg, hg+8), fully unrolled.
// 256-thread block = 2 rois. Grid = NROI/2 = 2048 blocks.
__global__ __launch_bounds__(256, 5) void proi_kernel(const float* __restrict__ rois,
                                                      float* __restrict__ out) {
    __shared__ float  wxs[2][16];
    __shared__ float  wys[2][16];
    __shared__ float  inva[2];
    __shared__ float4 partial[8][16];

    int tid   = threadIdx.x;
    int lane  = tid & 31;
    int warp  = tid >> 5;
    int roiIB = warp >> 2;              // roi within block: 0..1
    int wIR   = warp & 3;               // warp within roi: 0..3
    int li    = lane & 15;              // channel-group lane (c = 4*li..4*li+3)
    int half  = lane >> 4;
    int hg    = (wIR << 1) + half;      // y-phase 0..7

    int r = (blockIdx.x << 1) + roiIB;
    // output row r <-> roi storage (n*B + b_out), r = b_out*512 + n
    int b_out = r >> 9;
    int n     = r & (NPER - 1);
    const float* rp = rois + (n * BB + b_out) * 5;

    int   bidx = (int)__ldg(rp + 0);
    float x1   = __ldg(rp + 1);
    float y1   = __ldg(rp + 2);
    float x2   = __ldg(rp + 3);
    float y2   = __ldg(rp + 4);

    // Clamped 14-wide windows: tent weights outside the true box are exactly 0,
    // and base+13 <= 63 keeps every load in-bounds.
    int ix0 = min((int)floorf(x1), CLAMPB);   // x1 >= 0
    int iy0 = min((int)floorf(y1), CLAMPB);
    int ix1 = min(WW - 1, (int)ceilf(x2));
    int iy1 = min(HH - 1, (int)ceilf(y2));
    int nxW = ix1 - ix0 + 1;            // <= 14
    int nyW = iy1 - iy0 + 1;            // <= 14

    // One warp per roi computes the weights: lanes 0-15 -> wx, 16-31 -> wy.
    if (wIR == 0) {
        float lo   = (half == 0) ? x1 : y1;
        float hi   = (half == 0) ? x2 : y2;
        int   base = (half == 0) ? ix0 : iy0;
        float fi   = (float)(base + li);
        float w    = tentI(hi - fi) - tentI(lo - fi);
        if (half == 0) wxs[roiIB][li] = w;
        else           wys[roiIB][li] = w;
        if (lane == 0)
            inva[roiIB] = 1.0f / ((x2 - x1) * (y2 - y1));
    }
    __syncthreads();

    const float4* fbase = g_featT4 + (((bidx * HH + iy0) * WW + ix0) << 4) + li;

    float4 acc = make_float4(0.f, 0.f, 0.f, 0.f);

    // Row 1: j = hg (active unless nyW <= hg; nyW >= 5 so phases 0-4 always run)
    if (hg < nyW) {
        float wy = wys[roiIB][hg];
        const float4* fp = fbase + (hg * WW << 4);
        float4 racc = make_float4(0.f, 0.f, 0.f, 0.f);
#pragma unroll
        for (int ii = 0; ii < 14; ++ii) {
            if (ii < nxW) {
                float4 v = fp[ii << 4];
                float  w = wxs[roiIB][ii];
                racc.x = fmaf(w, v.x, racc.x);
                racc.y = fmaf(w, v.y, racc.y);
                racc.z = fmaf(w, v.z, racc.z);
                racc.w = fmaf(w, v.w, racc.w);
            }
        }
        acc.x = fmaf(wy, racc.x, acc.x);
        acc.y = fmaf(wy, racc.y, acc.y);
        acc.z = fmaf(wy, racc.z, acc.z);
        acc.w = fmaf(wy, racc.w, acc.w);
    }

    // Row 2: j = hg + 8 (guard also bounds wys index: hg+8 < nyW <= 14)
    if (hg + 8 < nyW) {
        float wy = wys[roiIB][hg + 8];
        const float4* fp = fbase + ((hg + 8) * WW << 4);
        float4 racc = make_float4(0.f, 0.f, 0.f, 0.f);
#pragma unroll
        for (int ii = 0; ii < 14; ++ii) {
            if (ii < nxW) {
                float4 v = fp[ii << 4];
                float  w = wxs[roiIB][ii];
                racc.x = fmaf(w, v.x, racc.x);
                racc.y = fmaf(w, v.y, racc.y);
                racc.z = fmaf(w, v.z, racc.z);
                racc.w = fmaf(w, v.w, racc.w);
            }
        }
        acc.x = fmaf(wy, racc.x, acc.x);
        acc.y = fmaf(wy, racc.y, acc.y);
        acc.z = fmaf(wy, racc.z, acc.z);
        acc.w = fmaf(wy, racc.w, acc.w);
    }

    // Combine the two halves of this warp.
    acc.x += __shfl_xor_sync(0xFFFFFFFFu, acc.x, 16, 32);
    acc.y += __shfl_xor_sync(0xFFFFFFFFu, acc.y, 16, 32);
    acc.z += __shfl_xor_sync(0xFFFFFFFFu, acc.z, 16, 32);
    acc.w += __shfl_xor_sync(0xFFFFFFFFu, acc.w, 16, 32);

    if (half == 0) partial[warp][li] = acc;
    __syncthreads();

    // Final combine across the 4 warps of each roi; 32 threads write 2 rois.
    if (tid < 32) {
        int rid = tid >> 4;
        int l   = tid & 15;
        float4 a = partial[(rid << 2) + 0][l];
        float4 b = partial[(rid << 2) + 1][l];
        float4 c = partial[(rid << 2) + 2][l];
        float4 d = partial[(rid << 2) + 3][l];
        float ia = inva[rid];
        float4 o = make_float4((a.x + b.x + c.x + d.x) * ia,
                               (a.y + b.y + c.y + d.y) * ia,
                               (a.z + b.z + c.z + d.z) * ia,
                               (a.w + b.w + c.w + d.w) * ia);
        int rr = (blockIdx.x << 1) + rid;
        ((float4*)out)[(rr << 4) + l] = o;
    }
}

extern "C" void kernel_launch(void* const* d_in, const int* in_sizes, int n_in,
                              void* d_out, int out_size) {
    const float* feature = (const float*)d_in[0];
    const float* rois    = (const float*)d_in[1];
    float* out           = (float*)d_out;

    dim3 tgrid(WW / 32, CC / 32, BB * HH);
    dim3 tblk(32, 32);
    transpose_nchw_nhwc<<<tgrid, tblk>>>(feature);

    proi_kernel<<<NROI / 2, 256>>>(rois, out);
}

// round 5
// speedup vs baseline: 1.6243x; 1.1233x over previous
#include <cuda_runtime.h>

#define BB 8
#define CC 64
#define HH 64
#define WW 64
#define NROI 4096
#define NPER 512   // rois per batch-outer index
#define CLAMPB 50  // 64 - 14: window base clamp so base+13 <= 63

// NHWC scratch copy of the feature map (8 MB), float4-aligned.
__device__ float4 g_featT4[BB * HH * WW * (CC / 4)];

// Antiderivative of the bilinear tent kernel max(0, 1-|t|), clipped.
__device__ __forceinline__ float tentI(float t) {
    t = fminf(1.0f, fmaxf(-1.0f, t));
    float a = t + 1.0f;
    float b = 1.0f - t;
    return (t < 0.0f) ? 0.5f * a * a : 1.0f - 0.5f * b * b;
}

// NCHW -> NHWC transpose, one 64(c)x64(x) tile per (b,y).
// float4 loads along x, float4 stores along c. 512 blocks x 256 threads.
__global__ __launch_bounds__(256) void transpose_nchw_nhwc(const float* __restrict__ feat) {
    __shared__ float tile[64][65];   // tile[x][c]
    int by = blockIdx.x;             // b*HH + y
    int b  = by >> 6;
    int y  = by & 63;
    int t  = threadIdx.x;

    int cRow = t >> 4;               // 0..15
    int x4   = (t & 15) << 2;        // 0,4,...,60
#pragma unroll
    for (int k = 0; k < 4; ++k) {
        int c = cRow + (k << 4);
        float4 v = *(const float4*)(feat + (((b * CC + c) * HH + y) * WW) + x4);
        tile[x4 + 0][c] = v.x;
        tile[x4 + 1][c] = v.y;
        tile[x4 + 2][c] = v.z;
        tile[x4 + 3][c] = v.w;
    }
    __syncthreads();

    int xRow = t >> 4;
    int c4   = (t & 15) << 2;
    float* dst = (float*)g_featT4;
#pragma unroll
    for (int k = 0; k < 4; ++k) {
        int x = xRow + (k << 4);
        float4 v = make_float4(tile[x][c4 + 0], tile[x][c4 + 1],
                               tile[x][c4 + 2], tile[x][c4 + 3]);
        *(float4*)(dst + ((size_t)(by * WW + x) * CC) + c4) = v;
    }
}

// 4 warps (128 lanes) per roi: 16 channel-lanes (float4) x 8-way y-split,
// 2 rows per thread (j = hg, hg+8), fully unrolled.
// 256-thread block = 2 rois. Grid = NROI/2 = 2048 blocks.
__global__ __launch_bounds__(256, 6) void proi_kernel(const float* __restrict__ rois,
                                                      float* __restrict__ out) {
    __shared__ float  wxs[2][16];
    __shared__ float  wys[2][16];
    __shared__ float  inva[2];
    __shared__ float4 partial[8][16];

    int tid   = threadIdx.x;
    int lane  = tid & 31;
    int warp  = tid >> 5;
    int roiIB = warp >> 2;              // roi within block: 0..1
    int wIR   = warp & 3;               // warp within roi: 0..3
    int li    = lane & 15;              // channel-group lane (c = 4*li..4*li+3)
    int half  = lane >> 4;
    int hg    = (wIR << 1) + half;      // y-phase 0..7

    int r = (blockIdx.x << 1) + roiIB;
    // output row r <-> roi storage (n*B + b_out), r = b_out*512 + n
    int b_out = r >> 9;
    int n     = r & (NPER - 1);
    const float* rp = rois + (n * BB + b_out) * 5;

    int   bidx = (int)__ldg(rp + 0);
    float x1   = __ldg(rp + 1);
    float y1   = __ldg(rp + 2);
    float x2   = __ldg(rp + 3);
    float y2   = __ldg(rp + 4);

    // Clamped 14-wide windows: tent weights outside the true box are exactly 0,
    // and base+13 <= 63 keeps every load in-bounds.
    int ix0 = min((int)floorf(x1), CLAMPB);   // x1 >= 0
    int iy0 = min((int)floorf(y1), CLAMPB);
    int ix1 = min(WW - 1, (int)ceilf(x2));
    int iy1 = min(HH - 1, (int)ceilf(y2));
    int nxW = ix1 - ix0 + 1;            // 5..14, uniform per roi
    int nyW = iy1 - iy0 + 1;            // 5..14, uniform per roi

    // One warp per roi computes the weights: lanes 0-15 -> wx, 16-31 -> wy.
    if (wIR == 0) {
        float lo   = (half == 0) ? x1 : y1;
        float hi   = (half == 0) ? x2 : y2;
        int   base = (half == 0) ? ix0 : iy0;
        float fi   = (float)(base + li);
        float w    = tentI(hi - fi) - tentI(lo - fi);
        if (half == 0) wxs[roiIB][li] = w;
        else           wys[roiIB][li] = w;
        if (lane == 0)
            inva[roiIB] = 1.0f / ((x2 - x1) * (y2 - y1));
    }
    __syncthreads();

    const float4* fbase = g_featT4 + (((bidx * HH + iy0) * WW + ix0) << 4) + li;

    float4 acc = make_float4(0.f, 0.f, 0.f, 0.f);

    // Row 1: j = hg (phases 0-4 always active since nyW >= 5)
    if (hg < nyW) {
        float wy = wys[roiIB][hg];
        const float4* fp = fbase + (hg * WW << 4);
        float4 racc = make_float4(0.f, 0.f, 0.f, 0.f);
#pragma unroll
        for (int ii = 0; ii < 14; ++ii) {
            if (ii < 5 || ii < nxW) {   // first 5 unconditional (nxW >= 5)
                float4 v = fp[ii << 4];
                float  w = wxs[roiIB][ii];
                racc.x = fmaf(w, v.x, racc.x);
                racc.y = fmaf(w, v.y, racc.y);
                racc.z = fmaf(w, v.z, racc.z);
                racc.w = fmaf(w, v.w, racc.w);
            }
        }
        acc.x = fmaf(wy, racc.x, acc.x);
        acc.y = fmaf(wy, racc.y, acc.y);
        acc.z = fmaf(wy, racc.z, acc.z);
        acc.w = fmaf(wy, racc.w, acc.w);
    }

    // Row 2: j = hg + 8
    if (hg + 8 < nyW) {
        float wy = wys[roiIB][hg + 8];
        const float4* fp = fbase + ((hg + 8) * WW << 4);
        float4 racc = make_float4(0.f, 0.f, 0.f, 0.f);
#pragma unroll
        for (int ii = 0; ii < 14; ++ii) {
            if (ii < 5 || ii < nxW) {
                float4 v = fp[ii << 4];
                float  w = wxs[roiIB][ii];
                racc.x = fmaf(w, v.x, racc.x);
                racc.y = fmaf(w, v.y, racc.y);
                racc.z = fmaf(w, v.z, racc.z);
                racc.w = fmaf(w, v.w, racc.w);
            }
        }
        acc.x = fmaf(wy, racc.x, acc.x);
        acc.y = fmaf(wy, racc.y, acc.y);
        acc.z = fmaf(wy, racc.z, acc.z);
        acc.w = fmaf(wy, racc.w, acc.w);
    }

    // Combine the two halves of this warp.
    acc.x += __shfl_xor_sync(0xFFFFFFFFu, acc.x, 16, 32);
    acc.y += __shfl_xor_sync(0xFFFFFFFFu, acc.y, 16, 32);
    acc.z += __shfl_xor_sync(0xFFFFFFFFu, acc.z, 16, 32);
    acc.w += __shfl_xor_sync(0xFFFFFFFFu, acc.w, 16, 32);

    if (half == 0) partial[warp][li] = acc;
    __syncthreads();

    // Final combine across the 4 warps of each roi; 32 threads write 2 rois.
    if (tid < 32) {
        int rid = tid >> 4;
        int l   = tid & 15;
        float4 a = partial[(rid << 2) + 0][l];
        float4 b = partial[(rid << 2) + 1][l];
        float4 c = partial[(rid << 2) + 2][l];
        float4 d = partial[(rid << 2) + 3][l];
        float ia = inva[rid];
        float4 o = make_float4((a.x + b.x + c.x + d.x) * ia,
                               (a.y + b.y + c.y + d.y) * ia,
                               (a.z + b.z + c.z + d.z) * ia,
                               (a.w + b.w + c.w + d.w) * ia);
        int rr = (blockIdx.x << 1) + rid;
        ((float4*)out)[(rr << 4) + l] = o;
    }
}

extern "C" void kernel_launch(void* const* d_in, const int* in_sizes, int n_in,
                              void* d_out, int out_size) {
    const float* feature = (const float*)d_in[0];
    const float* rois    = (const float*)d_in[1];
    float* out           = (float*)d_out;

    transpose_nchw_nhwc<<<BB * HH, 256>>>(feature);
    proi_kernel<<<NROI / 2, 256>>>(rois, out);
}